// round 3
// baseline (speedup 1.0000x reference)
#include <cuda_runtime.h>
#include <math.h>

// Problem constants (fixed shapes per dataset)
#define HD   4096   // hidden size
#define IS   2048   // routed expert intermediate
#define NE   16     // experts
#define NK   4      // top-k
#define SIW  2048   // shared expert intermediate
#define TMAX 4096   // max tokens (2*2048)

#define BM   128
#define BN   256
#define BKT  16     // K elements per pipeline stage
#define LSTR 20     // padded smem row stride in floats -> conflict-free fragment reads

#define SM_A_FLOATS (BM * LSTR)            // 2560
#define SM_B_FLOATS (BN * LSTR)            // 5120
#define SM_STAGE    (SM_A_FLOATS + SM_B_FLOATS)   // 7680 floats
#define SM_BYTES    (2 * SM_STAGE * 4)     // 61440 bytes

// ---------------- static device scratch (no allocations allowed) ----------------
__device__ int   d_cnt[NE];
__device__ int   d_tok[NE * TMAX];
__device__ float d_wgt[NE * TMAX];
__device__ float d_bufG[(size_t)NE * TMAX * IS];   // routed gate proj, then z in-place
__device__ float d_bufU[(size_t)NE * TMAX * IS];   // routed up proj
__device__ float d_sG[(size_t)TMAX * SIW];         // shared gate, then z in-place
__device__ float d_sU[(size_t)TMAX * SIW];         // shared up

__device__ __forceinline__ float* bufptr(int s) {
    switch (s) {
        case 0:  return d_bufG;
        case 1:  return d_bufU;
        case 2:  return d_sG;
        default: return d_sU;
    }
}

// ---------------- helpers ----------------
__device__ __forceinline__ unsigned f2tf32(float f) {
    unsigned r;
    asm("cvt.rna.tf32.f32 %0, %1;" : "=r"(r) : "f"(f));
    return r;
}

__device__ __forceinline__ void mma_tf32(float* d, const unsigned* a, unsigned b0, unsigned b1) {
    asm volatile(
        "mma.sync.aligned.m16n8k8.row.col.f32.tf32.tf32.f32 "
        "{%0,%1,%2,%3}, {%4,%5,%6,%7}, {%8,%9}, {%0,%1,%2,%3};"
        : "+f"(d[0]), "+f"(d[1]), "+f"(d[2]), "+f"(d[3])
        : "r"(a[0]), "r"(a[1]), "r"(a[2]), "r"(a[3]), "r"(b0), "r"(b1));
}

// ---------------- router ----------------
__global__ void zero_cnt_kernel() {
    if (threadIdx.x < NE) d_cnt[threadIdx.x] = 0;
}

__global__ void router_kernel(const float* __restrict__ x,
                              const float* __restrict__ gw,
                              const float* __restrict__ bias) {
    __shared__ float sx[HD];
    __shared__ float sc[NE];
    int t = blockIdx.x;
    const float4* xr = (const float4*)(x + (size_t)t * HD);
    for (int i = threadIdx.x; i < HD / 4; i += blockDim.x)
        ((float4*)sx)[i] = xr[i];
    __syncthreads();

    int warp = threadIdx.x >> 5, lane = threadIdx.x & 31;
    int nwarp = blockDim.x >> 5;
    for (int e = warp; e < NE; e += nwarp) {
        const float* w = gw + (size_t)e * HD;
        float s = 0.f;
        for (int i = lane; i < HD; i += 32) s = fmaf(sx[i], w[i], s);
        #pragma unroll
        for (int o = 16; o > 0; o >>= 1) s += __shfl_xor_sync(0xffffffffu, s, o);
        if (lane == 0) sc[e] = 1.f / (1.f + expf(-s)) + bias[e];
    }
    __syncthreads();

    if (threadIdx.x == 0) {
        float v[NE];
        #pragma unroll
        for (int e = 0; e < NE; e++) v[e] = sc[e];
        int   idx[NK];
        float wv[NK];
        float sum = 0.f;
        #pragma unroll
        for (int k = 0; k < NK; k++) {
            int bi = 0; float bv = -1e30f;
            #pragma unroll
            for (int e = 0; e < NE; e++) if (v[e] > bv) { bv = v[e]; bi = e; }
            idx[k] = bi; wv[k] = bv; v[bi] = -1e30f; sum += bv;
        }
        float inv = 1.f / (sum + 1e-20f);
        #pragma unroll
        for (int k = 0; k < NK; k++) {
            int e   = idx[k];
            int pos = atomicAdd(&d_cnt[e], 1);
            d_tok[e * TMAX + pos] = t;
            d_wgt[e * TMAX + pos] = wv[k] * inv;
        }
    }
}

// ---------------- tf32 tensor-core GEMM: C[M,N] = A[M,K] * B[N,K]^T ----------------
// CTA tile 128x256, 8 warps (2 along M x 4 along N), warp tile 64x64.
// tf32 conversion happens ONCE at smem store; inner loop is pure LDS + HMMA.
// MODE 0: plain (shared expert).  M passed in.
// MODE 1: gather A rows from X via per-expert token list; C = per-expert buffer.
// MODE 2: A = per-expert buffer; scatter C rows to out via token list with atomicAdd.
template<int MODE>
__global__ __launch_bounds__(256, 1)
void gemm_tf32(const float* __restrict__ Aext,
               const float* __restrict__ Bext,
               float* __restrict__ Cext,
               int aSel, int cSel,
               int M, int K, int N,
               long long sB, long long sAC) {
    int e = blockIdx.z;
    const int* tok = d_tok + e * TMAX;
    if (MODE != 0) M = d_cnt[e];
    if ((int)blockIdx.y * BM >= M) return;

    const float* A = (aSel >= 0) ? bufptr(aSel) : Aext;
    float*       C = (cSel >= 0) ? bufptr(cSel) : Cext;
    const float* B = Bext + (size_t)e * sB;
    if (MODE == 1) C += (size_t)e * sAC;
    if (MODE == 2) A += (size_t)e * sAC;

    extern __shared__ float smem[];

    int tid  = threadIdx.x;
    int lane = tid & 31;
    int warp = tid >> 5;
    int wm   = warp & 1;      // 2 warps along M (64 rows each)
    int wn   = warp >> 1;     // 4 warps along N (64 cols each)

    // ---- loader mapping: quad q = tid&3 (16B each), row = tid>>2 (+64*it) ----
    int lq   = (tid & 3) * 4;           // float offset within 16-float k-slice
    int lr   = tid >> 2;                // 0..63

    // A rows handled by this thread: lr and lr+64
    const float* aP[2];
    {
        #pragma unroll
        for (int it = 0; it < 2; it++) {
            int r = blockIdx.y * BM + lr + it * 64;
            if (MODE == 1) {
                int tr = (r < M) ? tok[r] : tok[0];
                aP[it] = A + (size_t)tr * K + lq;
            } else {
                int rr = (r < M) ? r : (M - 1);
                aP[it] = A + (size_t)rr * K + lq;
            }
        }
    }
    // B rows: lr + {0,64,128,192}
    const float* bP = B + (size_t)(blockIdx.x * BN + lr) * K + lq;

    float acc[4][8][4];
    #pragma unroll
    for (int i = 0; i < 4; i++)
        #pragma unroll
        for (int j = 0; j < 8; j++)
            #pragma unroll
            for (int q = 0; q < 4; q++) acc[i][j][q] = 0.f;

    int NT = K / BKT;

    float4 aV[2], bV[4];

    // fragment base indices (in floats) within a stage
    int fr = (lane >> 2);            // 0..7
    int fc = (lane & 3);             // 0..3
    int aBase = (wm * 64 + fr) * LSTR + fc;
    int bBase = (wn * 64 + fr) * LSTR + fc;

    // ---- prologue: load stage 0 ----
    #pragma unroll
    for (int it = 0; it < 2; it++) aV[it] = *(const float4*)(aP[it]);
    #pragma unroll
    for (int it = 0; it < 4; it++) bV[it] = *(const float4*)(bP + (size_t)it * 64 * K);

    {
        float* sA = smem;
        float* sB2 = smem + SM_A_FLOATS;
        #pragma unroll
        for (int it = 0; it < 2; it++) {
            uint4 u = make_uint4(f2tf32(aV[it].x), f2tf32(aV[it].y),
                                 f2tf32(aV[it].z), f2tf32(aV[it].w));
            *(uint4*)&sA[(lr + it * 64) * LSTR + lq] = u;
        }
        #pragma unroll
        for (int it = 0; it < 4; it++) {
            uint4 u = make_uint4(f2tf32(bV[it].x), f2tf32(bV[it].y),
                                 f2tf32(bV[it].z), f2tf32(bV[it].w));
            *(uint4*)&sB2[(lr + it * 64) * LSTR + lq] = u;
        }
    }
    __syncthreads();

    for (int s = 0; s < NT; s++) {
        // issue next-stage global loads early (latency hidden by compute below)
        if (s + 1 < NT) {
            int k0 = (s + 1) * BKT;
            #pragma unroll
            for (int it = 0; it < 2; it++) aV[it] = *(const float4*)(aP[it] + k0);
            #pragma unroll
            for (int it = 0; it < 4; it++) bV[it] = *(const float4*)(bP + (size_t)it * 64 * K + k0);
        }

        const unsigned* as = (const unsigned*)(smem + (s & 1) * SM_STAGE);
        const unsigned* bs = as + SM_A_FLOATS;

        #pragma unroll
        for (int ks = 0; ks < BKT; ks += 8) {
            unsigned a[4][4];
            #pragma unroll
            for (int i = 0; i < 4; i++) {
                int base = aBase + i * 16 * LSTR + ks;
                a[i][0] = as[base];
                a[i][1] = as[base + 8 * LSTR];
                a[i][2] = as[base + 4];
                a[i][3] = as[base + 8 * LSTR + 4];
            }
            #pragma unroll
            for (int j = 0; j < 8; j++) {
                int base = bBase + j * 8 * LSTR + ks;
                unsigned b0 = bs[base];
                unsigned b1 = bs[base + 4];
                #pragma unroll
                for (int i = 0; i < 4; i++)
                    mma_tf32(acc[i][j], a[i], b0, b1);
            }
        }

        if (s + 1 < NT) {
            float* sA = smem + ((s + 1) & 1) * SM_STAGE;
            float* sB2 = sA + SM_A_FLOATS;
            #pragma unroll
            for (int it = 0; it < 2; it++) {
                uint4 u = make_uint4(f2tf32(aV[it].x), f2tf32(aV[it].y),
                                     f2tf32(aV[it].z), f2tf32(aV[it].w));
                *(uint4*)&sA[(lr + it * 64) * LSTR + lq] = u;
            }
            #pragma unroll
            for (int it = 0; it < 4; it++) {
                uint4 u = make_uint4(f2tf32(bV[it].x), f2tf32(bV[it].y),
                                     f2tf32(bV[it].z), f2tf32(bV[it].w));
                *(uint4*)&sB2[(lr + it * 64) * LSTR + lq] = u;
            }
        }
        __syncthreads();
    }

    // ---- epilogue ----
    #pragma unroll
    for (int i = 0; i < 4; i++) {
        int r0 = blockIdx.y * BM + wm * 64 + i * 16 + (lane >> 2);
        #pragma unroll
        for (int j = 0; j < 8; j++) {
            int c0 = blockIdx.x * BN + wn * 64 + j * 8 + 2 * (lane & 3);
            if (MODE == 2) {
                if (r0 < M) {
                    int tr = tok[r0];
                    atomicAdd(C + (size_t)tr * N + c0,     acc[i][j][0]);
                    atomicAdd(C + (size_t)tr * N + c0 + 1, acc[i][j][1]);
                }
                if (r0 + 8 < M) {
                    int tr = tok[r0 + 8];
                    atomicAdd(C + (size_t)tr * N + c0,     acc[i][j][2]);
                    atomicAdd(C + (size_t)tr * N + c0 + 1, acc[i][j][3]);
                }
            } else {
                if (r0 < M) {
                    float2* cp = (float2*)(C + (size_t)r0 * N + c0);
                    *cp = make_float2(acc[i][j][0], acc[i][j][1]);
                }
                if (r0 + 8 < M) {
                    float2* cp = (float2*)(C + (size_t)(r0 + 8) * N + c0);
                    *cp = make_float2(acc[i][j][2], acc[i][j][3]);
                }
            }
        }
    }
}

// ---------------- activation kernels ----------------
__device__ __forceinline__ float silu_f(float v) {
    return v / (1.f + expf(-v));
}

__global__ void routed_act_kernel() {
    int e   = blockIdx.y;
    int row = blockIdx.x;
    if (row >= d_cnt[e]) return;
    float  w    = d_wgt[e * TMAX + row];
    size_t base = ((size_t)e * TMAX + row) * IS;
    float4*       g4 = (float4*)(d_bufG + base);
    const float4* u4 = (const float4*)(d_bufU + base);
    for (int i = threadIdx.x; i < IS / 4; i += blockDim.x) {
        float4 g = g4[i], u = u4[i], z;
        z.x = silu_f(g.x) * u.x * w;
        z.y = silu_f(g.y) * u.y * w;
        z.z = silu_f(g.z) * u.z * w;
        z.w = silu_f(g.w) * u.w * w;
        g4[i] = z;
    }
}

__global__ void shared_act_kernel() {
    int    row  = blockIdx.x;
    size_t base = (size_t)row * SIW;
    float4*       g4 = (float4*)(d_sG + base);
    const float4* u4 = (const float4*)(d_sU + base);
    for (int i = threadIdx.x; i < SIW / 4; i += blockDim.x) {
        float4 g = g4[i], u = u4[i], z;
        z.x = silu_f(g.x) * u.x;
        z.y = silu_f(g.y) * u.y;
        z.z = silu_f(g.z) * u.z;
        z.w = silu_f(g.w) * u.w;
        g4[i] = z;
    }
}

// ---------------- launch ----------------
extern "C" void kernel_launch(void* const* d_in, const int* in_sizes, int n_in,
                              void* d_out, int out_size) {
    const float* x    = (const float*)d_in[0];   // [2,2048,H]
    const float* gw   = (const float*)d_in[1];   // [E,H]
    const float* bias = (const float*)d_in[2];   // [E]
    const float* Wg   = (const float*)d_in[3];   // [E,I,H]
    const float* Wu   = (const float*)d_in[4];   // [E,I,H]
    const float* Wd   = (const float*)d_in[5];   // [E,H,I]
    const float* Sg   = (const float*)d_in[6];   // [SI,H]
    const float* Su   = (const float*)d_in[7];   // [SI,H]
    const float* Sd   = (const float*)d_in[8];   // [H,SI]
    float* out = (float*)d_out;

    int Tn = in_sizes[0] / HD;          // 4096 tokens
    int mt = (Tn + BM - 1) / BM;

    static int smem_set = 0;
    if (!smem_set) {
        cudaFuncSetAttribute(gemm_tf32<0>, cudaFuncAttributeMaxDynamicSharedMemorySize, SM_BYTES);
        cudaFuncSetAttribute(gemm_tf32<1>, cudaFuncAttributeMaxDynamicSharedMemorySize, SM_BYTES);
        cudaFuncSetAttribute(gemm_tf32<2>, cudaFuncAttributeMaxDynamicSharedMemorySize, SM_BYTES);
        smem_set = 1;
    }

    zero_cnt_kernel<<<1, 32>>>();
    router_kernel<<<Tn, 128>>>(x, gw, bias);

    // shared expert: gs = X @ Sg^T, us = X @ Su^T, zs = silu(gs)*us, out = zs @ Sd^T
    gemm_tf32<0><<<dim3(SIW / BN, mt, 1), 256, SM_BYTES>>>(x, Sg, nullptr, -1, 2, Tn, HD, SIW, 0, 0);
    gemm_tf32<0><<<dim3(SIW / BN, mt, 1), 256, SM_BYTES>>>(x, Su, nullptr, -1, 3, Tn, HD, SIW, 0, 0);
    shared_act_kernel<<<Tn, 256>>>();
    gemm_tf32<0><<<dim3(HD / BN, mt, 1), 256, SM_BYTES>>>(nullptr, Sd, out, 2, -1, Tn, SIW, HD, 0, 0);

    // routed experts (sparse): gather rows of X per expert, gated MLP, scatter-add to out
    gemm_tf32<1><<<dim3(IS / BN, mt, NE), 256, SM_BYTES>>>(x, Wg, nullptr, -1, 0, 0, HD, IS,
                                                           (long long)IS * HD, (long long)TMAX * IS);
    gemm_tf32<1><<<dim3(IS / BN, mt, NE), 256, SM_BYTES>>>(x, Wu, nullptr, -1, 1, 0, HD, IS,
                                                           (long long)IS * HD, (long long)TMAX * IS);
    routed_act_kernel<<<dim3(Tn, NE), 256>>>();
    gemm_tf32<2><<<dim3(HD / BN, mt, NE), 256, SM_BYTES>>>(nullptr, Wd, out, 0, -1, 0, IS, HD,
                                                           (long long)HD * IS, (long long)TMAX * IS);
    (void)n_in; (void)out_size;
}

// round 5
// speedup vs baseline: 1.9964x; 1.9964x over previous
#include <cuda_runtime.h>
#include <math.h>
#include <stdint.h>

// Problem constants
#define HD   4096
#define IS   2048
#define NE   16
#define NK   4
#define SIW  2048
#define TMAX 4096

// GEMM tile: CTA 128x128, 4 warps (2Mx2N), warp tile 64x64, K-chunk 32
#define BM   128
#define BN   128
#define BKT  32
#define LSTR 36                              // padded row stride (floats)
#define SM_A_FLOATS (BM * LSTR)              // 4608
#define SM_STAGE    (2 * SM_A_FLOATS)        // A + B per stage = 9216 floats
#define STAGE_BYTES (SM_STAGE * 4)           // 36864
#define DSMEM_BYTES (2 * STAGE_BYTES)        // 73728

// ---------------- static device scratch ----------------
__device__ int   d_cnt[NE];
__device__ int   d_tok[NE * TMAX];
__device__ float d_wgt[NE * TMAX];
__device__ float d_bufG[(size_t)NE * TMAX * IS];   // routed gate proj -> z (rounded)
__device__ float d_bufU[(size_t)NE * TMAX * IS];   // routed up proj
__device__ float d_sG[(size_t)TMAX * SIW];         // shared gate -> z (rounded)
__device__ float d_sU[(size_t)TMAX * SIW];         // shared up
// tf32-pre-rounded operands
__device__ float d_xr [(size_t)TMAX * HD];
__device__ float d_Wgr[(size_t)NE * IS * HD];
__device__ float d_Wur[(size_t)NE * IS * HD];
__device__ float d_Wdr[(size_t)NE * HD * IS];
__device__ float d_Sgr[(size_t)SIW * HD];
__device__ float d_Sur[(size_t)SIW * HD];
__device__ float d_Sdr[(size_t)HD * SIW];

__device__ __forceinline__ float* selw(int s) {
    switch (s) {
        case 0:  return d_bufG;
        case 1:  return d_bufU;
        case 2:  return d_sG;
        case 3:  return d_sU;
        case 4:  return d_xr;
        case 5:  return d_Wgr;
        case 6:  return d_Wur;
        case 7:  return d_Wdr;
        case 8:  return d_Sgr;
        case 9:  return d_Sur;
        default: return d_Sdr;
    }
}

// ---------------- helpers ----------------
__device__ __forceinline__ uint32_t smem_u32(const void* p) {
    uint32_t a;
    asm("{ .reg .u64 t; cvta.to.shared.u64 t, %1; cvt.u32.u64 %0, t; }" : "=r"(a) : "l"(p));
    return a;
}
__device__ __forceinline__ unsigned f2tf32(float f) {
    unsigned r;
    asm("cvt.rna.tf32.f32 %0, %1;" : "=r"(r) : "f"(f));
    return r;
}
#define CPA16(dst, src) \
    asm volatile("cp.async.cg.shared.global [%0], [%1], 16;" :: "r"(dst), "l"(src))
#define CPA_COMMIT() asm volatile("cp.async.commit_group;")
#define CPA_WAIT(n)  asm volatile("cp.async.wait_group %0;" :: "n"(n))

__device__ __forceinline__ void mma_tf32(float* d, const unsigned* a, unsigned b0, unsigned b1) {
    asm volatile(
        "mma.sync.aligned.m16n8k8.row.col.f32.tf32.tf32.f32 "
        "{%0,%1,%2,%3}, {%4,%5,%6,%7}, {%8,%9}, {%0,%1,%2,%3};"
        : "+f"(d[0]), "+f"(d[1]), "+f"(d[2]), "+f"(d[3])
        : "r"(a[0]), "r"(a[1]), "r"(a[2]), "r"(a[3]), "r"(b0), "r"(b1));
}

// ---------------- router ----------------
__global__ void zero_cnt_kernel() {
    if (threadIdx.x < NE) d_cnt[threadIdx.x] = 0;
}

__global__ void router_kernel(const float* __restrict__ x,
                              const float* __restrict__ gw,
                              const float* __restrict__ bias) {
    __shared__ float sx[HD];
    __shared__ float sc[NE];
    int t = blockIdx.x;
    const float4* xr = (const float4*)(x + (size_t)t * HD);
    for (int i = threadIdx.x; i < HD / 4; i += blockDim.x)
        ((float4*)sx)[i] = xr[i];
    __syncthreads();

    int warp = threadIdx.x >> 5, lane = threadIdx.x & 31;
    int nwarp = blockDim.x >> 5;
    for (int e = warp; e < NE; e += nwarp) {
        const float* w = gw + (size_t)e * HD;
        float s = 0.f;
        for (int i = lane; i < HD; i += 32) s = fmaf(sx[i], w[i], s);
        #pragma unroll
        for (int o = 16; o > 0; o >>= 1) s += __shfl_xor_sync(0xffffffffu, s, o);
        if (lane == 0) sc[e] = 1.f / (1.f + expf(-s)) + bias[e];
    }
    __syncthreads();

    if (threadIdx.x == 0) {
        float v[NE];
        #pragma unroll
        for (int e = 0; e < NE; e++) v[e] = sc[e];
        int idx[NK]; float wv[NK]; float sum = 0.f;
        #pragma unroll
        for (int k = 0; k < NK; k++) {
            int bi = 0; float bv = -1e30f;
            #pragma unroll
            for (int e = 0; e < NE; e++) if (v[e] > bv) { bv = v[e]; bi = e; }
            idx[k] = bi; wv[k] = bv; v[bi] = -1e30f; sum += bv;
        }
        float inv = 1.f / (sum + 1e-20f);
        #pragma unroll
        for (int k = 0; k < NK; k++) {
            int e = idx[k];
            int pos = atomicAdd(&d_cnt[e], 1);
            d_tok[e * TMAX + pos] = t;
            d_wgt[e * TMAX + pos] = wv[k] * inv;
        }
    }
}

// ---------------- tf32 pre-rounding pass ----------------
__global__ void round_kernel(const float4* __restrict__ in, int dstSel, int n4) {
    float4* out = (float4*)selw(dstSel);
    int stride = gridDim.x * blockDim.x;
    for (int i = blockIdx.x * blockDim.x + threadIdx.x; i < n4; i += stride) {
        float4 v = in[i];
        float4 o;
        o.x = __uint_as_float(f2tf32(v.x));
        o.y = __uint_as_float(f2tf32(v.y));
        o.z = __uint_as_float(f2tf32(v.z));
        o.w = __uint_as_float(f2tf32(v.w));
        out[i] = o;
    }
}

// ---------------- tf32 mma.sync GEMM: C[M,N] = A[M,K] * B[N,K]^T ----------------
// Inner loop is pure LDS+HMMA (operands pre-rounded to tf32 in gmem).
// MODE 0: plain. MODE 1: gather A rows via token list, C = per-expert buffer.
// MODE 2: A = per-expert buffer, scatter-add C rows to out via token list.
template<int MODE>
__global__ __launch_bounds__(128)
void gemm_mma(int aSel, int bSel, int cSel, float* __restrict__ Cext,
              int M, int K, int N, long long sB, long long sAC) {
    int e = blockIdx.z;
    const int* tok = d_tok + e * TMAX;
    if (MODE != 0) M = d_cnt[e];
    if ((int)blockIdx.y * BM >= M) return;

    const float* A = selw(aSel);
    const float* B = selw(bSel) + (size_t)e * sB;
    float* C = (cSel >= 0) ? selw(cSel) : Cext;
    if (MODE == 1) C += (size_t)e * sAC;
    if (MODE == 2) A += (size_t)e * sAC;

    extern __shared__ float smem[];
    uint32_t sbase = smem_u32(smem);

    int tid  = threadIdx.x;
    int lane = tid & 31;
    int warp = tid >> 5;
    int wm   = warp & 1;     // 2 warps along M (64 rows each)
    int wn   = warp >> 1;    // 2 warps along N (64 cols each)

    // ---- loader: thread owns (tid&7)*4 float offset, rows i*16 + (tid>>3) ----
    int lq = (tid & 7) * 4;
    int lr = tid >> 3;               // 0..15
    const float* aP[8];
    const float* bP[8];
    #pragma unroll
    for (int i = 0; i < 8; i++) {
        int r = blockIdx.y * BM + i * 16 + lr;
        int src;
        if (MODE == 1) src = (r < M) ? tok[r] : tok[0];
        else           src = (r < M) ? r : (M - 1);
        aP[i] = A + (size_t)src * K + lq;
        bP[i] = B + (size_t)(blockIdx.x * BN + i * 16 + lr) * K + lq;
    }
    uint32_t dOffA = (uint32_t)((lr * LSTR + lq) * 4);
    uint32_t dOffB = dOffA + (uint32_t)(SM_A_FLOATS * 4);

    float acc[4][8][4];
    #pragma unroll
    for (int i = 0; i < 4; i++)
        #pragma unroll
        for (int j = 0; j < 8; j++)
            #pragma unroll
            for (int q = 0; q < 4; q++) acc[i][j][q] = 0.f;

    int NT = K / BKT;

    auto load_chunk = [&](int c) {
        uint32_t sb = sbase + (uint32_t)(c & 1) * STAGE_BYTES;
        int k0 = c * BKT;
        #pragma unroll
        for (int i = 0; i < 8; i++) {
            uint32_t ro = (uint32_t)(i * 16 * LSTR * 4);
            CPA16(sb + dOffA + ro, aP[i] + k0);
            CPA16(sb + dOffB + ro, bP[i] + k0);
        }
        CPA_COMMIT();
    };

    load_chunk(0);
    load_chunk(1);

    int aBase = (wm * 64 + (lane >> 2)) * LSTR + (lane & 3);
    int bBase = (wn * 64 + (lane >> 2)) * LSTR + (lane & 3);

    for (int s = 0; s < NT; s++) {
        if (s + 1 < NT) CPA_WAIT(1); else CPA_WAIT(0);
        __syncthreads();

        const unsigned* as = (const unsigned*)(smem + (s & 1) * SM_STAGE);
        const unsigned* bs = as + SM_A_FLOATS;

        #pragma unroll
        for (int ks = 0; ks < BKT; ks += 8) {
            unsigned a[4][4];
            #pragma unroll
            for (int i = 0; i < 4; i++) {
                int base = aBase + i * 16 * LSTR + ks;
                a[i][0] = as[base];
                a[i][1] = as[base + 8 * LSTR];
                a[i][2] = as[base + 4];
                a[i][3] = as[base + 8 * LSTR + 4];
            }
            #pragma unroll
            for (int j = 0; j < 8; j++) {
                int bb = bBase + j * 8 * LSTR + ks;
                unsigned b0 = bs[bb];
                unsigned b1 = bs[bb + 4];
                #pragma unroll
                for (int i = 0; i < 4; i++)
                    mma_tf32(acc[i][j], a[i], b0, b1);
            }
        }

        __syncthreads();               // all warps done reading before overwrite
        if (s + 2 < NT) load_chunk(s + 2);
    }

    // ---- epilogue ----
    #pragma unroll
    for (int i = 0; i < 4; i++) {
        int r0 = blockIdx.y * BM + wm * 64 + i * 16 + (lane >> 2);
        #pragma unroll
        for (int j = 0; j < 8; j++) {
            int c0 = blockIdx.x * BN + wn * 64 + j * 8 + 2 * (lane & 3);
            if (MODE == 2) {
                if (r0 < M) {
                    int tr = tok[r0];
                    atomicAdd(C + (size_t)tr * N + c0,     acc[i][j][0]);
                    atomicAdd(C + (size_t)tr * N + c0 + 1, acc[i][j][1]);
                }
                if (r0 + 8 < M) {
                    int tr = tok[r0 + 8];
                    atomicAdd(C + (size_t)tr * N + c0,     acc[i][j][2]);
                    atomicAdd(C + (size_t)tr * N + c0 + 1, acc[i][j][3]);
                }
            } else {
                if (r0 < M) {
                    *(float2*)(C + (size_t)r0 * N + c0) =
                        make_float2(acc[i][j][0], acc[i][j][1]);
                }
                if (r0 + 8 < M) {
                    *(float2*)(C + (size_t)(r0 + 8) * N + c0) =
                        make_float2(acc[i][j][2], acc[i][j][3]);
                }
            }
        }
    }
}

// ---------------- activation kernels (store tf32-rounded z) ----------------
__device__ __forceinline__ float silu_f(float v) {
    return v / (1.f + expf(-v));
}
__device__ __forceinline__ float rnd(float v) {
    return __uint_as_float(f2tf32(v));
}

__global__ void routed_act_kernel() {
    int e = blockIdx.y;
    int row = blockIdx.x;
    if (row >= d_cnt[e]) return;
    float w = d_wgt[e * TMAX + row];
    size_t base = ((size_t)e * TMAX + row) * IS;
    float4* g4 = (float4*)(d_bufG + base);
    const float4* u4 = (const float4*)(d_bufU + base);
    for (int i = threadIdx.x; i < IS / 4; i += blockDim.x) {
        float4 g = g4[i], u = u4[i], z;
        z.x = rnd(silu_f(g.x) * u.x * w);
        z.y = rnd(silu_f(g.y) * u.y * w);
        z.z = rnd(silu_f(g.z) * u.z * w);
        z.w = rnd(silu_f(g.w) * u.w * w);
        g4[i] = z;
    }
}

__global__ void shared_act_kernel() {
    int row = blockIdx.x;
    size_t base = (size_t)row * SIW;
    float4* g4 = (float4*)(d_sG + base);
    const float4* u4 = (const float4*)(d_sU + base);
    for (int i = threadIdx.x; i < SIW / 4; i += blockDim.x) {
        float4 g = g4[i], u = u4[i], z;
        z.x = rnd(silu_f(g.x) * u.x);
        z.y = rnd(silu_f(g.y) * u.y);
        z.z = rnd(silu_f(g.z) * u.z);
        z.w = rnd(silu_f(g.w) * u.w);
        g4[i] = z;
    }
}

// ---------------- launch ----------------
extern "C" void kernel_launch(void* const* d_in, const int* in_sizes, int n_in,
                              void* d_out, int out_size) {
    const float* x    = (const float*)d_in[0];
    const float* gw   = (const float*)d_in[1];
    const float* bias = (const float*)d_in[2];
    const float* Wg   = (const float*)d_in[3];
    const float* Wu   = (const float*)d_in[4];
    const float* Wd   = (const float*)d_in[5];
    const float* Sg   = (const float*)d_in[6];
    const float* Su   = (const float*)d_in[7];
    const float* Sd   = (const float*)d_in[8];
    float* out = (float*)d_out;

    int Tn = in_sizes[0] / HD;            // 4096 tokens
    int mt = (Tn + BM - 1) / BM;          // 32

    static int smem_set = 0;
    if (!smem_set) {
        cudaFuncSetAttribute(gemm_mma<0>, cudaFuncAttributeMaxDynamicSharedMemorySize, DSMEM_BYTES);
        cudaFuncSetAttribute(gemm_mma<1>, cudaFuncAttributeMaxDynamicSharedMemorySize, DSMEM_BYTES);
        cudaFuncSetAttribute(gemm_mma<2>, cudaFuncAttributeMaxDynamicSharedMemorySize, DSMEM_BYTES);
        smem_set = 1;
    }

    zero_cnt_kernel<<<1, 32>>>();
    router_kernel<<<Tn, 128>>>(x, gw, bias);

    // tf32 pre-rounding (RNA) of all GEMM operands
    round_kernel<<<2048, 256>>>((const float4*)x,  4,  (int)((size_t)Tn * HD / 4));
    round_kernel<<<4096, 256>>>((const float4*)Wg, 5,  (int)((size_t)NE * IS * HD / 4));
    round_kernel<<<4096, 256>>>((const float4*)Wu, 6,  (int)((size_t)NE * IS * HD / 4));
    round_kernel<<<4096, 256>>>((const float4*)Wd, 7,  (int)((size_t)NE * HD * IS / 4));
    round_kernel<<<1024, 256>>>((const float4*)Sg, 8,  (int)((size_t)SIW * HD / 4));
    round_kernel<<<1024, 256>>>((const float4*)Su, 9,  (int)((size_t)SIW * HD / 4));
    round_kernel<<<1024, 256>>>((const float4*)Sd, 10, (int)((size_t)HD * SIW / 4));

    // shared expert
    gemm_mma<0><<<dim3(SIW / BN, mt, 1), 128, DSMEM_BYTES>>>(4, 8, 2, nullptr, Tn, HD, SIW, 0, 0);
    gemm_mma<0><<<dim3(SIW / BN, mt, 1), 128, DSMEM_BYTES>>>(4, 9, 3, nullptr, Tn, HD, SIW, 0, 0);
    shared_act_kernel<<<Tn, 256>>>();
    gemm_mma<0><<<dim3(HD / BN, mt, 1), 128, DSMEM_BYTES>>>(2, 10, -1, out, Tn, SIW, HD, 0, 0);

    // routed experts (sparse)
    gemm_mma<1><<<dim3(IS / BN, TMAX / BM, NE), 128, DSMEM_BYTES>>>(
        4, 5, 0, nullptr, 0, HD, IS, (long long)IS * HD, (long long)TMAX * IS);
    gemm_mma<1><<<dim3(IS / BN, TMAX / BM, NE), 128, DSMEM_BYTES>>>(
        4, 6, 1, nullptr, 0, HD, IS, (long long)IS * HD, (long long)TMAX * IS);
    routed_act_kernel<<<dim3(Tn, NE), 256>>>();
    gemm_mma<2><<<dim3(HD / BN, TMAX / BM, NE), 128, DSMEM_BYTES>>>(
        0, 7, -1, out, 0, IS, HD, (long long)HD * IS, (long long)TMAX * IS);

    (void)n_in; (void)out_size;
}

// round 7
// speedup vs baseline: 2.1231x; 1.0635x over previous
#include <cuda_runtime.h>
#include <math.h>
#include <stdint.h>

// Problem constants
#define HD   4096
#define IS   2048
#define NE   16
#define NK   4
#define SIW  2048
#define TMAX 4096

// GEMM tile: CTA 128x128, 4 warps (2Mx2N), warp tile 64x64, K-chunk 32
#define BM   128
#define BN   128
#define BKT  32
#define LSTR 36                              // padded row stride (floats)
#define SM_A_FLOATS (BM * LSTR)              // 4608
#define SM_STAGE    (2 * SM_A_FLOATS)        // A + B per stage = 9216 floats
#define STAGE_BYTES (SM_STAGE * 4)           // 36864
#define DSMEM_BYTES (2 * STAGE_BYTES)        // 73728

// ---------------- static device scratch ----------------
__device__ int   d_cnt[NE];
__device__ int   d_tok[NE * TMAX];
__device__ float d_wgt[NE * TMAX];
__device__ float d_bufG[(size_t)NE * TMAX * IS];   // routed gate proj -> z (rounded)
__device__ float d_bufU[(size_t)NE * TMAX * IS];   // routed up proj
__device__ float d_sG[(size_t)TMAX * SIW];         // shared gate -> z (rounded)
__device__ float d_sU[(size_t)TMAX * SIW];         // shared up
__device__ float d_xr[(size_t)TMAX * HD];          // tf32-rounded x

__device__ __forceinline__ float* selw(int s) {
    switch (s) {
        case 0:  return d_bufG;
        case 1:  return d_bufU;
        case 2:  return d_sG;
        case 3:  return d_sU;
        default: return d_xr;
    }
}

// ---------------- helpers ----------------
__device__ __forceinline__ uint32_t smem_u32(const void* p) {
    uint32_t a;
    asm("{ .reg .u64 t; cvta.to.shared.u64 t, %1; cvt.u32.u64 %0, t; }" : "=r"(a) : "l"(p));
    return a;
}
__device__ __forceinline__ unsigned f2tf32(float f) {
    unsigned r;
    asm("cvt.rna.tf32.f32 %0, %1;" : "=r"(r) : "f"(f));
    return r;
}
__device__ __forceinline__ float rndf(float v) {
    return __uint_as_float(f2tf32(v));
}
#define CPA16(dst, src) \
    asm volatile("cp.async.cg.shared.global [%0], [%1], 16;" :: "r"(dst), "l"(src))
#define CPA_COMMIT() asm volatile("cp.async.commit_group;")
#define CPA_WAIT(n)  asm volatile("cp.async.wait_group %0;" :: "n"(n))

__device__ __forceinline__ void mma_tf32(float* d, const unsigned* a, unsigned b0, unsigned b1) {
    asm volatile(
        "mma.sync.aligned.m16n8k8.row.col.f32.tf32.tf32.f32 "
        "{%0,%1,%2,%3}, {%4,%5,%6,%7}, {%8,%9}, {%0,%1,%2,%3};"
        : "+f"(d[0]), "+f"(d[1]), "+f"(d[2]), "+f"(d[3])
        : "r"(a[0]), "r"(a[1]), "r"(a[2]), "r"(a[3]), "r"(b0), "r"(b1));
}

// ---------------- router ----------------
__global__ void zero_cnt_kernel() {
    if (threadIdx.x < NE) d_cnt[threadIdx.x] = 0;
}

__global__ void router_kernel(const float* __restrict__ x,
                              const float* __restrict__ gw,
                              const float* __restrict__ bias) {
    __shared__ float sx[HD];
    __shared__ float sc[NE];
    int t = blockIdx.x;
    const float4* xr = (const float4*)(x + (size_t)t * HD);
    for (int i = threadIdx.x; i < HD / 4; i += blockDim.x)
        ((float4*)sx)[i] = xr[i];
    __syncthreads();

    int warp = threadIdx.x >> 5, lane = threadIdx.x & 31;
    int nwarp = blockDim.x >> 5;
    for (int e = warp; e < NE; e += nwarp) {
        const float* w = gw + (size_t)e * HD;
        float s = 0.f;
        for (int i = lane; i < HD; i += 32) s = fmaf(sx[i], w[i], s);
        #pragma unroll
        for (int o = 16; o > 0; o >>= 1) s += __shfl_xor_sync(0xffffffffu, s, o);
        if (lane == 0) sc[e] = 1.f / (1.f + expf(-s)) + bias[e];
    }
    __syncthreads();

    if (threadIdx.x == 0) {
        float v[NE];
        #pragma unroll
        for (int e = 0; e < NE; e++) v[e] = sc[e];
        int idx[NK]; float wv[NK]; float sum = 0.f;
        #pragma unroll
        for (int k = 0; k < NK; k++) {
            int bi = 0; float bv = -1e30f;
            #pragma unroll
            for (int e = 0; e < NE; e++) if (v[e] > bv) { bv = v[e]; bi = e; }
            idx[k] = bi; wv[k] = bv; v[bi] = -1e30f; sum += bv;
        }
        float inv = 1.f / (sum + 1e-20f);
        #pragma unroll
        for (int k = 0; k < NK; k++) {
            int e = idx[k];
            int pos = atomicAdd(&d_cnt[e], 1);
            d_tok[e * TMAX + pos] = t;
            d_wgt[e * TMAX + pos] = wv[k] * inv;
        }
    }
}

// ---------------- tf32 pre-rounding (x only) ----------------
__global__ void round_kernel(const float4* __restrict__ in, int n4) {
    float4* out = (float4*)d_xr;
    int stride = gridDim.x * blockDim.x;
    for (int i = blockIdx.x * blockDim.x + threadIdx.x; i < n4; i += stride) {
        float4 v = in[i];
        float4 o;
        o.x = rndf(v.x); o.y = rndf(v.y); o.z = rndf(v.z); o.w = rndf(v.w);
        out[i] = o;
    }
}

// ---------------- tf32 mma.sync GEMM: C[M,N] = A[M,K] * B[N,K]^T ----------------
// A: pre-rounded scratch buffer (cp.async). B: RAW fp32 weights, rounded to tf32
// in-register (LDG -> cvt.rna -> STS), eliminating the separate round passes.
// Single __syncthreads per K-chunk.
// MODE 0: plain. MODE 1: gather A rows via token list, C = per-expert buffer.
// MODE 2: A = per-expert buffer, scatter-add C rows to out via token list.
template<int MODE>
__global__ __launch_bounds__(128)
void gemm_mma(int aSel, const float* __restrict__ Bext, int cSel,
              float* __restrict__ Cext,
              int M, int K, int N, long long sB, long long sAC) {
    int e = blockIdx.z;
    const int* tok = d_tok + e * TMAX;
    if (MODE != 0) M = d_cnt[e];
    if ((int)blockIdx.y * BM >= M) return;

    const float* A = selw(aSel);
    const float* B = Bext + (size_t)e * sB;
    float* C = (cSel >= 0) ? selw(cSel) : Cext;
    if (MODE == 1) C += (size_t)e * sAC;
    if (MODE == 2) A += (size_t)e * sAC;

    extern __shared__ float smem[];
    uint32_t sbase = smem_u32(smem);

    int tid  = threadIdx.x;
    int lane = tid & 31;
    int warp = tid >> 5;
    int wm   = warp & 1;     // 2 warps along M (64 rows each)
    int wn   = warp >> 1;    // 2 warps along N (64 cols each)

    // ---- loader: thread owns (tid&7)*4 float offset, rows i*16 + (tid>>3) ----
    int lq = (tid & 7) * 4;
    int lr = tid >> 3;               // 0..15
    const float* aP[8];
    const float* bP[8];
    #pragma unroll
    for (int i = 0; i < 8; i++) {
        int r = blockIdx.y * BM + i * 16 + lr;
        int src;
        if (MODE == 1) src = (r < M) ? tok[r] : tok[0];
        else           src = (r < M) ? r : (M - 1);
        aP[i] = A + (size_t)src * K + lq;
        bP[i] = B + (size_t)(blockIdx.x * BN + i * 16 + lr) * K + lq;
    }
    uint32_t dOffA = (uint32_t)((lr * LSTR + lq) * 4);
    int      sOffB = SM_A_FLOATS + lr * LSTR + lq;

    float acc[4][8][4];
    #pragma unroll
    for (int i = 0; i < 4; i++)
        #pragma unroll
        for (int j = 0; j < 8; j++)
            #pragma unroll
            for (int q = 0; q < 4; q++) acc[i][j][q] = 0.f;

    int NT = K / BKT;
    float4 bReg[8];

    auto load_chunkA = [&](int c) {
        uint32_t sb = sbase + (uint32_t)(c & 1) * STAGE_BYTES;
        int k0 = c * BKT;
        #pragma unroll
        for (int i = 0; i < 8; i++)
            CPA16(sb + dOffA + (uint32_t)(i * 16 * LSTR * 4), aP[i] + k0);
        CPA_COMMIT();
    };
    auto ldg_B = [&](int c) {
        int k0 = c * BKT;
        #pragma unroll
        for (int i = 0; i < 8; i++)
            bReg[i] = *(const float4*)(bP[i] + k0);
    };
    auto sts_B = [&](int c) {
        float* st = smem + (c & 1) * SM_STAGE + sOffB;
        #pragma unroll
        for (int i = 0; i < 8; i++) {
            float4 v = bReg[i];
            float4 o;
            o.x = rndf(v.x); o.y = rndf(v.y); o.z = rndf(v.z); o.w = rndf(v.w);
            *(float4*)(st + i * 16 * LSTR) = o;
        }
    };

    // prologue: stage 0
    load_chunkA(0);
    ldg_B(0);
    sts_B(0);

    int aBase = (wm * 64 + (lane >> 2)) * LSTR + (lane & 3);
    int bBase = (wn * 64 + (lane >> 2)) * LSTR + (lane & 3);

    for (int s = 0; s < NT; s++) {
        CPA_WAIT(0);
        __syncthreads();      // stage s (A via cp.async, B via STS) fully visible;
                              // all warps done with stage s-1

        if (s + 1 < NT) {
            ldg_B(s + 1);     // long-latency LDG issued before compute
            load_chunkA(s + 1);
        }

        const unsigned* as = (const unsigned*)(smem + (s & 1) * SM_STAGE);
        const unsigned* bs = as + SM_A_FLOATS;

        #pragma unroll
        for (int ks = 0; ks < BKT; ks += 8) {
            unsigned a[4][4];
            #pragma unroll
            for (int i = 0; i < 4; i++) {
                int base = aBase + i * 16 * LSTR + ks;
                a[i][0] = as[base];
                a[i][1] = as[base + 8 * LSTR];
                a[i][2] = as[base + 4];
                a[i][3] = as[base + 8 * LSTR + 4];
            }
            #pragma unroll
            for (int j = 0; j < 8; j++) {
                int bb = bBase + j * 8 * LSTR + ks;
                unsigned b0 = bs[bb];
                unsigned b1 = bs[bb + 4];
                #pragma unroll
                for (int i = 0; i < 4; i++)
                    mma_tf32(acc[i][j], a[i], b0, b1);
            }
        }

        if (s + 1 < NT) sts_B(s + 1);   // writes stage (s+1)&1: nobody reads it
                                        // until after next iteration's barrier
    }

    // ---- epilogue ----
    #pragma unroll
    for (int i = 0; i < 4; i++) {
        int r0 = blockIdx.y * BM + wm * 64 + i * 16 + (lane >> 2);
        #pragma unroll
        for (int j = 0; j < 8; j++) {
            int c0 = blockIdx.x * BN + wn * 64 + j * 8 + 2 * (lane & 3);
            if (MODE == 2) {
                if (r0 < M) {
                    int tr = tok[r0];
                    atomicAdd(C + (size_t)tr * N + c0,     acc[i][j][0]);
                    atomicAdd(C + (size_t)tr * N + c0 + 1, acc[i][j][1]);
                }
                if (r0 + 8 < M) {
                    int tr = tok[r0 + 8];
                    atomicAdd(C + (size_t)tr * N + c0,     acc[i][j][2]);
                    atomicAdd(C + (size_t)tr * N + c0 + 1, acc[i][j][3]);
                }
            } else {
                if (r0 < M) {
                    *(float2*)(C + (size_t)r0 * N + c0) =
                        make_float2(acc[i][j][0], acc[i][j][1]);
                }
                if (r0 + 8 < M) {
                    *(float2*)(C + (size_t)(r0 + 8) * N + c0) =
                        make_float2(acc[i][j][2], acc[i][j][3]);
                }
            }
        }
    }
}

// ---------------- activation kernels (store tf32-rounded z) ----------------
__device__ __forceinline__ float silu_f(float v) {
    return v / (1.f + expf(-v));
}

__global__ void routed_act_kernel() {
    int e = blockIdx.y;
    int row = blockIdx.x;
    if (row >= d_cnt[e]) return;
    float w = d_wgt[e * TMAX + row];
    size_t base = ((size_t)e * TMAX + row) * IS;
    float4* g4 = (float4*)(d_bufG + base);
    const float4* u4 = (const float4*)(d_bufU + base);
    for (int i = threadIdx.x; i < IS / 4; i += blockDim.x) {
        float4 g = g4[i], u = u4[i], z;
        z.x = rndf(silu_f(g.x) * u.x * w);
        z.y = rndf(silu_f(g.y) * u.y * w);
        z.z = rndf(silu_f(g.z) * u.z * w);
        z.w = rndf(silu_f(g.w) * u.w * w);
        g4[i] = z;
    }
}

__global__ void shared_act_kernel() {
    int row = blockIdx.x;
    size_t base = (size_t)row * SIW;
    float4* g4 = (float4*)(d_sG + base);
    const float4* u4 = (const float4*)(d_sU + base);
    for (int i = threadIdx.x; i < SIW / 4; i += blockDim.x) {
        float4 g = g4[i], u = u4[i], z;
        z.x = rndf(silu_f(g.x) * u.x);
        z.y = rndf(silu_f(g.y) * u.y);
        z.z = rndf(silu_f(g.z) * u.z);
        z.w = rndf(silu_f(g.w) * u.w);
        g4[i] = z;
    }
}

// ---------------- launch ----------------
extern "C" void kernel_launch(void* const* d_in, const int* in_sizes, int n_in,
                              void* d_out, int out_size) {
    const float* x    = (const float*)d_in[0];
    const float* gw   = (const float*)d_in[1];
    const float* bias = (const float*)d_in[2];
    const float* Wg   = (const float*)d_in[3];
    const float* Wu   = (const float*)d_in[4];
    const float* Wd   = (const float*)d_in[5];
    const float* Sg   = (const float*)d_in[6];
    const float* Su   = (const float*)d_in[7];
    const float* Sd   = (const float*)d_in[8];
    float* out = (float*)d_out;

    int Tn = in_sizes[0] / HD;            // 4096 tokens
    int mt = (Tn + BM - 1) / BM;          // 32

    static int smem_set = 0;
    if (!smem_set) {
        cudaFuncSetAttribute(gemm_mma<0>, cudaFuncAttributeMaxDynamicSharedMemorySize, DSMEM_BYTES);
        cudaFuncSetAttribute(gemm_mma<1>, cudaFuncAttributeMaxDynamicSharedMemorySize, DSMEM_BYTES);
        cudaFuncSetAttribute(gemm_mma<2>, cudaFuncAttributeMaxDynamicSharedMemorySize, DSMEM_BYTES);
        smem_set = 1;
    }

    zero_cnt_kernel<<<1, 32>>>();
    router_kernel<<<Tn, 128>>>(x, gw, bias);

    // tf32 pre-rounding of x only (weights rounded in-register inside GEMMs)
    round_kernel<<<2048, 256>>>((const float4*)x, (int)((size_t)Tn * HD / 4));

    // shared expert
    gemm_mma<0><<<dim3(SIW / BN, mt, 1), 128, DSMEM_BYTES>>>(4, Sg, 2, nullptr, Tn, HD, SIW, 0, 0);
    gemm_mma<0><<<dim3(SIW / BN, mt, 1), 128, DSMEM_BYTES>>>(4, Su, 3, nullptr, Tn, HD, SIW, 0, 0);
    shared_act_kernel<<<Tn, 256>>>();
    gemm_mma<0><<<dim3(HD / BN, mt, 1), 128, DSMEM_BYTES>>>(2, Sd, -1, out, Tn, SIW, HD, 0, 0);

    // routed experts (sparse)
    gemm_mma<1><<<dim3(IS / BN, TMAX / BM, NE), 128, DSMEM_BYTES>>>(
        4, Wg, 0, nullptr, 0, HD, IS, (long long)IS * HD, (long long)TMAX * IS);
    gemm_mma<1><<<dim3(IS / BN, TMAX / BM, NE), 128, DSMEM_BYTES>>>(
        4, Wu, 1, nullptr, 0, HD, IS, (long long)IS * HD, (long long)TMAX * IS);
    routed_act_kernel<<<dim3(Tn, NE), 256>>>();
    gemm_mma<2><<<dim3(HD / BN, TMAX / BM, NE), 128, DSMEM_BYTES>>>(
        0, Wd, -1, out, 0, IS, HD, (long long)HD * IS, (long long)TMAX * IS);

    (void)n_in; (void)out_size;
}